// round 4
// baseline (speedup 1.0000x reference)
#include <cuda_runtime.h>
#include <cstdint>

#define BATCH   32
#define CIN     64
#define COUT    64
#define HH      64
#define WW      64
#define HOUT    62
#define WOUT    62
#define KTOT    576          // CIN * 3 * 3
#define BLOCK   64
#define KCHUNK  32
#define XSTRIDE 36           // 32 batches + 4 pad; rows 144B (16B-aligned), conflict-free reads
#define WSTRIDE 33           // bank = (c + kk) % 32 -> conflict-free scalar reads/stores
#define NCHUNK  18           // 576 / 32

typedef unsigned long long u64;

__device__ __forceinline__ u64 pk(float lo, float hi) {
    u64 r;
    asm("mov.b64 %0, {%1, %2};" : "=l"(r) : "f"(lo), "f"(hi));
    return r;
}
__device__ __forceinline__ void upk(u64 v, float& lo, float& hi) {
    asm("mov.b64 {%0, %1}, %2;" : "=f"(lo), "=f"(hi) : "l"(v));
}
// Packed dual-FMA on the Blackwell f32x2 pipe (2x FFMA rate)
__device__ __forceinline__ void fma2(u64& d, u64 a, u64 b) {
    asm("fma.rn.f32x2 %0, %1, %2, %0;" : "+l"(d) : "l"(a), "l"(b));
}
__device__ __forceinline__ void cp4(uint32_t dst, const float* src) {
    asm volatile("cp.async.ca.shared.global [%0], [%1], 4;" :: "r"(dst), "l"(src) : "memory");
}
__device__ __forceinline__ void cpcommit() {
    asm volatile("cp.async.commit_group;" ::: "memory");
}
__device__ __forceinline__ void cpwait1() {
    asm volatile("cp.async.wait_group 1;" ::: "memory");
}

__global__ void __launch_bounds__(BLOCK)
lc2d_kernel(const float* __restrict__ features,
            const float* __restrict__ weights,
            const float* __restrict__ bias,
            float* __restrict__ out)
{
    // 3-deep x ring + 2-deep w ping-pong: 13824 + 16896 = 30720 B -> 7 CTAs/SM
    __shared__ float x_s[3][KCHUNK][XSTRIDE];
    __shared__ float w_s[2][COUT][WSTRIDE];

    const int tid = threadIdx.x;
    const int w   = blockIdx.x;
    const int h   = blockIdx.y;

    // compute mapping: warp spans all batches, 32 couts (fewer smem bytes/warp)
    const int bg = tid & 3;      // batches bg*8 .. bg*8+7
    const int cg = tid >> 2;     // couts  cg*4 .. cg*4+3

    // x-gather mapping (lanes vary over batch -> 2-way smem store conflicts max)
    const int bb = tid & 15;
    const int kq = tid >> 4;     // 0..3, each covers 8 k-values

    const float* wloc  = weights  + (size_t)(h * WOUT + w) * (COUT * KTOT);
    const float* fbase = features + h * WW + w;

    // w register relay: one full chunk (row c=tid, 32 floats = 8 float4)
    float4 rel[8];

    auto ldg_w = [&](int ch) {
        const float* src = wloc + tid * KTOT + ch * KCHUNK;
        #pragma unroll
        for (int i = 0; i < 8; i++)
            rel[i] = *(const float4*)(src + i * 4);
    };
    auto sts_w = [&](int b) {
        float* dst = &w_s[b][tid][0];     // scalar STS: bank=(tid+kk)%32 conflict-free
        #pragma unroll
        for (int i = 0; i < 8; i++) {
            dst[i * 4 + 0] = rel[i].x;
            dst[i * 4 + 1] = rel[i].y;
            dst[i * 4 + 2] = rel[i].z;
            dst[i * 4 + 3] = rel[i].w;
        }
    };
    // gather x chunk ch into ring slot (16x cp.async 4B, one commit)
    auto issue_x = [&](int ch, int slot) {
        #pragma unroll
        for (int i = 0; i < 8; i++) {
            int k   = kq * 8 + i;
            int r   = ch * KCHUNK + k;
            int cin = r / 9;
            int f   = r - cin * 9;
            int ii  = f / 3;
            int jj  = f - ii * 3;
            const float* src = fbase + cin * (HH * WW) + ii * WW + jj
                             + (size_t)bb * (CIN * HH * WW);
            uint32_t dst = (uint32_t)__cvta_generic_to_shared(&x_s[slot][k][bb]);
            cp4(dst,      src);
            cp4(dst + 64, src + (size_t)16 * (CIN * HH * WW));   // batch bb+16
        }
        cpcommit();
    };

    // ---- prologue: w0 -> buf0, w1 -> regs; x0, x1 in flight ----
    ldg_w(0);
    issue_x(0, 0);
    issue_x(1, 1);
    sts_w(0);
    ldg_w(1);

    u64 acc[4][4];   // [batch-pair p][cout j]
    #pragma unroll
    for (int p = 0; p < 4; p++)
        #pragma unroll
        for (int j = 0; j < 4; j++) acc[p][j] = 0ULL;

    int xc = 0;
    #pragma unroll 1
    for (int ch = 0; ch < NCHUNK; ch++) {
        // one group committed per iter (prologue committed 2) => wait_group 1
        // guarantees x(ch) landed.
        cpwait1();
        __syncthreads();   // publish x(ch), w(ch); ring slot (ch+2)%3 free; buf (ch+1)&1 free

        if (ch + 1 < NCHUNK) sts_w((ch + 1) & 1);
        if (ch + 2 < NCHUNK) {
            ldg_w(ch + 2);
            int xn = xc + 2; if (xn >= 3) xn -= 3;
            issue_x(ch + 2, xn);          // commits its group
        } else {
            cpcommit();                   // empty group keeps the count
        }

        const float* wb = &w_s[ch & 1][0][0];
        const float* xb = &x_s[xc][0][bg * 8];

        #pragma unroll
        for (int kk = 0; kk < KCHUNK; kk++) {
            // 8 batches: one LDS.128 pair -> four u64 batch-pairs, zero movs
            ulonglong2 xa = *(const ulonglong2*)(xb + kk * XSTRIDE);
            ulonglong2 xd = *(const ulonglong2*)(xb + kk * XSTRIDE + 4);
            // 4 couts: conflict-free scalar LDS + duplicate into pairs
            float w0 = wb[(cg * 4 + 0) * WSTRIDE + kk];
            float w1 = wb[(cg * 4 + 1) * WSTRIDE + kk];
            float w2 = wb[(cg * 4 + 2) * WSTRIDE + kk];
            float w3 = wb[(cg * 4 + 3) * WSTRIDE + kk];
            u64 wp0 = pk(w0, w0), wp1 = pk(w1, w1);
            u64 wp2 = pk(w2, w2), wp3 = pk(w3, w3);

            fma2(acc[0][0], xa.x, wp0); fma2(acc[1][0], xa.y, wp0);
            fma2(acc[2][0], xd.x, wp0); fma2(acc[3][0], xd.y, wp0);
            fma2(acc[0][1], xa.x, wp1); fma2(acc[1][1], xa.y, wp1);
            fma2(acc[2][1], xd.x, wp1); fma2(acc[3][1], xd.y, wp1);
            fma2(acc[0][2], xa.x, wp2); fma2(acc[1][2], xa.y, wp2);
            fma2(acc[2][2], xd.x, wp2); fma2(acc[3][2], xd.y, wp2);
            fma2(acc[0][3], xa.x, wp3); fma2(acc[1][3], xa.y, wp3);
            fma2(acc[2][3], xd.x, wp3); fma2(acc[3][3], xd.y, wp3);
        }

        xc++; if (xc >= 3) xc -= 3;
    }

    // ---- epilogue: unpack, add bias, scattered STG.32 ----
    const float* bl = bias + (h * WOUT + w) * COUT;
    const int c0 = cg * 4;
    float bv[4];
    #pragma unroll
    for (int j = 0; j < 4; j++) bv[j] = bl[c0 + j];

    #pragma unroll
    for (int p = 0; p < 4; p++) {
        const int b0 = bg * 8 + 2 * p;
        #pragma unroll
        for (int j = 0; j < 4; j++) {
            float lo, hi;
            upk(acc[p][j], lo, hi);
            out[(( b0      * COUT + c0 + j) * HOUT + h) * WOUT + w] = lo + bv[j];
            out[(((b0 + 1) * COUT + c0 + j) * HOUT + h) * WOUT + w] = hi + bv[j];
        }
    }
}

extern "C" void kernel_launch(void* const* d_in, const int* in_sizes, int n_in,
                              void* d_out, int out_size)
{
    const float* features = nullptr;
    const float* weights  = nullptr;
    const float* bias     = nullptr;
    for (int i = 0; i < n_in; i++) {
        if      (in_sizes[i] == BATCH * CIN * HH * WW)        features = (const float*)d_in[i];
        else if (in_sizes[i] == HOUT * WOUT * COUT * CIN * 9) weights  = (const float*)d_in[i];
        else if (in_sizes[i] == HOUT * WOUT * COUT)           bias     = (const float*)d_in[i];
    }
    float* out = (float*)d_out;

    dim3 grid(WOUT, HOUT);
    lc2d_kernel<<<grid, BLOCK>>>(features, weights, bias, out);
}

// round 7
// speedup vs baseline: 2.5876x; 2.5876x over previous
#include <cuda_runtime.h>
#include <cstdint>

#define BATCH   32
#define CIN     64
#define COUT    64
#define HH      64
#define WW      64
#define HOUT    62
#define WOUT    62
#define KTOT    576          // CIN * 3 * 3
#define BLOCK   128
#define KCHUNK  32
#define NCHUNK  18           // 576 / 32
#define WT      68           // w_t row stride (floats): 16B-aligned, swizzle-friendly

typedef unsigned long long u64;

// persistent scratch: features transposed to [cin][h][w][batch] (batch contiguous)
__device__ float g_xposed[CIN * HH * WW * BATCH];   // 33.5 MB

__device__ __forceinline__ u64 pk(float lo, float hi) {
    u64 r;
    asm("mov.b64 %0, {%1, %2};" : "=l"(r) : "f"(lo), "f"(hi));
    return r;
}
__device__ __forceinline__ void upk(u64 v, float& lo, float& hi) {
    asm("mov.b64 {%0, %1}, %2;" : "=f"(lo), "=f"(hi) : "l"(v));
}
// Packed dual-FMA on the Blackwell f32x2 pipe (2x FFMA rate)
__device__ __forceinline__ void fma2(u64& d, u64 a, u64 b) {
    asm("fma.rn.f32x2 %0, %1, %2, %0;" : "+l"(d) : "l"(a), "l"(b));
}
__device__ __forceinline__ void cp16(uint32_t dst, const float* src) {
    asm volatile("cp.async.cg.shared.global [%0], [%1], 16;" :: "r"(dst), "l"(src) : "memory");
}
__device__ __forceinline__ void cpcommit() {
    asm volatile("cp.async.commit_group;" ::: "memory");
}
__device__ __forceinline__ void cpwait1() {
    asm volatile("cp.async.wait_group 1;" ::: "memory");
}

// ---------------- kernel 1: transpose features [b][cin][h][w] -> [cin][h][w][b] ----
__global__ void __launch_bounds__(256)
xpose_kernel(const float* __restrict__ features)
{
    __shared__ float t[32][33];
    const int cin = blockIdx.x >> 6;
    const int hh  = blockIdx.x & 63;
    const int ww0 = blockIdx.y << 5;
    const int tx = threadIdx.x & 31;
    const int ty = threadIdx.x >> 5;   // 0..7

    #pragma unroll
    for (int i = 0; i < 4; i++) {
        int b = ty + 8 * i;
        t[b][tx] = features[((b * CIN + cin) * HH + hh) * WW + ww0 + tx]; // coalesced read
    }
    __syncthreads();
    #pragma unroll
    for (int i = 0; i < 4; i++) {
        int wwi = ty + 8 * i;
        g_xposed[((cin * HH + hh) * WW + ww0 + wwi) * BATCH + tx] = t[tx][wwi]; // coalesced write
    }
}

// ---------------- kernel 2: locally-connected GEMM per (h,w) ------------------------
__global__ void __launch_bounds__(BLOCK, 6)
lc2d_kernel(const float* __restrict__ weights,
            const float* __restrict__ bias,
            float* __restrict__ out)
{
    __shared__ float x_s[3][KCHUNK][BATCH];   // 12288 B, packed: LDS.128 conflict-free
    __shared__ float w_t[2][KCHUNK][WT];      // 17408 B, k-major + XOR swizzle

    const int tid = threadIdx.x;
    const int w   = blockIdx.x;
    const int h   = blockIdx.y;

    // compute mapping: thread tile 4 batches x 4 couts
    const int bg  = tid & 7;                  // batches bg*4 .. bg*4+3
    const int cg  = (tid >> 3) & 3;
    const int wid = tid >> 5;
    const int c0  = wid * 16 + cg * 4;        // couts c0 .. c0+3

    // w-loader mapping: 4 rows (c = cb+16u) x one 16B k-segment (qq)
    const int qq = tid & 7;
    const int cb = tid >> 3;                  // 0..15

    const float* wloc  = weights + (size_t)(h * WOUT + w) * (COUT * KTOT);
    const float* fbase = g_xposed + (size_t)(h * WW + w) * BATCH;

    float4 rel[4];   // w register relay (one chunk ahead of smem)

    auto ldg_w = [&](int ch) {
        const float* src = wloc + ch * KCHUNK + qq * 4;
        #pragma unroll
        for (int u = 0; u < 4; u++)
            rel[u] = *(const float4*)(src + (size_t)(cb + 16 * u) * KTOT);
    };
    // k-major store with swizzle: physical col = c ^ ((kk>>2)<<2)  -> conflict-free
    auto sts_w = [&](int buf) {
        #pragma unroll
        for (int u = 0; u < 4; u++) {
            const int c = cb + 16 * u;
            const float* v = &rel[u].x;
            #pragma unroll
            for (int e = 0; e < 4; e++) {
                const int kk = qq * 4 + e;
                w_t[buf][kk][c ^ ((kk >> 2) << 2)] = v[e];
            }
        }
    };
    // x gather: 2 coalesced 16B cp.async per thread (batch-contiguous source)
    auto issue_x = [&](int ch, int slot) {
        #pragma unroll
        for (int s = 0; s < 2; s++) {
            const int idx = tid + s * BLOCK;
            const int k   = idx >> 3;
            const int seg = idx & 7;
            const int r   = ch * KCHUNK + k;
            const int cin = r / 9;
            const int f   = r - cin * 9;
            const int ii  = f / 3;
            const int jj  = f - ii * 3;
            const float* src = fbase + cin * (HH * WW * BATCH)
                             + ii * (WW * BATCH) + jj * BATCH + seg * 4;
            uint32_t dst = (uint32_t)__cvta_generic_to_shared(&x_s[slot][k][seg * 4]);
            cp16(dst, src);
        }
        cpcommit();
    };

    // ---- prologue: w0 -> buf0, w1 -> regs; x0, x1 in flight (2 groups committed) ----
    ldg_w(0);
    issue_x(0, 0);
    issue_x(1, 1);
    sts_w(0);
    ldg_w(1);

    u64 acc[2][4];   // [batch-pair p][cout j]
    #pragma unroll
    for (int p = 0; p < 2; p++)
        #pragma unroll
        for (int j = 0; j < 4; j++) acc[p][j] = 0ULL;

    int xc = 0;
    #pragma unroll 1
    for (int ch = 0; ch < NCHUNK; ch++) {
        // exactly one group committed per iter => wait_group 1 guarantees x(ch) landed
        cpwait1();
        __syncthreads();   // publish x(ch), w(ch); ring slot (ch+2)%3 and w-buf free

        if (ch + 1 < NCHUNK) sts_w((ch + 1) & 1);
        if (ch + 2 < NCHUNK) {
            ldg_w(ch + 2);
            int xn = xc + 2; if (xn >= 3) xn -= 3;
            issue_x(ch + 2, xn);          // commits its group
        } else {
            cpcommit();                   // empty group keeps the count
        }

        const int wbuf = ch & 1;
        #pragma unroll
        for (int kk = 0; kk < KCHUNK; kk++) {
            // 4 batches: one LDS.128 (8 distinct 16B addrs spanning all banks, 1 wf)
            ulonglong2 xv = *(const ulonglong2*)(&x_s[xc][kk][bg * 4]);
            // 4 couts: one LDS.128 from swizzled k-major tile (broadcast x8, 1 wf)
            float4 wv = *(const float4*)(&w_t[wbuf][kk][c0 ^ ((kk >> 2) << 2)]);
            u64 wp0 = pk(wv.x, wv.x), wp1 = pk(wv.y, wv.y);
            u64 wp2 = pk(wv.z, wv.z), wp3 = pk(wv.w, wv.w);

            fma2(acc[0][0], xv.x, wp0); fma2(acc[1][0], xv.y, wp0);
            fma2(acc[0][1], xv.x, wp1); fma2(acc[1][1], xv.y, wp1);
            fma2(acc[0][2], xv.x, wp2); fma2(acc[1][2], xv.y, wp2);
            fma2(acc[0][3], xv.x, wp3); fma2(acc[1][3], xv.y, wp3);
        }

        xc++; if (xc >= 3) xc -= 3;
    }

    // ---- epilogue: unpack, add bias, scattered STG.32 ----
    const float* bl = bias + (h * WOUT + w) * COUT;
    float bv[4];
    #pragma unroll
    for (int j = 0; j < 4; j++) bv[j] = bl[c0 + j];

    #pragma unroll
    for (int p = 0; p < 2; p++) {
        const int b0 = bg * 4 + 2 * p;
        #pragma unroll
        for (int j = 0; j < 4; j++) {
            float lo, hi;
            upk(acc[p][j], lo, hi);
            out[(( b0      * COUT + c0 + j) * HOUT + h) * WOUT + w] = lo + bv[j];
            out[(((b0 + 1) * COUT + c0 + j) * HOUT + h) * WOUT + w] = hi + bv[j];
        }
    }
}

extern "C" void kernel_launch(void* const* d_in, const int* in_sizes, int n_in,
                              void* d_out, int out_size)
{
    const float* features = nullptr;
    const float* weights  = nullptr;
    const float* bias     = nullptr;
    for (int i = 0; i < n_in; i++) {
        if      (in_sizes[i] == BATCH * CIN * HH * WW)        features = (const float*)d_in[i];
        else if (in_sizes[i] == HOUT * WOUT * COUT * CIN * 9) weights  = (const float*)d_in[i];
        else if (in_sizes[i] == HOUT * WOUT * COUT)           bias     = (const float*)d_in[i];
    }
    float* out = (float*)d_out;

    // 1) transpose features -> [cin][h][w][batch]   (~12 us, stream-ordered)
    xpose_kernel<<<dim3(CIN * HH, WW / 32), 256>>>(features);
    // 2) main locally-connected GEMM
    lc2d_kernel<<<dim3(WOUT, HOUT), BLOCK>>>(weights, bias, out);
}

// round 8
// speedup vs baseline: 2.6639x; 1.0295x over previous
#include <cuda_runtime.h>
#include <cstdint>

#define BATCH   32
#define CIN     64
#define COUT    64
#define HH      64
#define WW      64
#define HOUT    62
#define WOUT    62
#define KTOT    576          // CIN * 3 * 3
#define BLOCK   128
#define KCHUNK  32
#define NCHUNK  18           // 576 / 32
#define WT      68           // w_t row stride: 68 % 32 == 4 (swizzle-friendly), 16B-aligned

typedef unsigned long long u64;

// persistent scratch: features transposed to [cin][h][w][batch] (batch contiguous)
__device__ float g_xposed[CIN * HH * WW * BATCH];   // 33.5 MB

// dynamic smem layout (51200 B): x[2][2][32][32] then w[2][2][32][WT]
#define XS_FLOATS (2 * 2 * KCHUNK * BATCH)            // 4096
#define WS_FLOATS (2 * 2 * KCHUNK * WT)               // 8704
#define SMEM_BYTES ((XS_FLOATS + WS_FLOATS) * 4)      // 51200

__device__ __forceinline__ u64 pk(float lo, float hi) {
    u64 r;
    asm("mov.b64 %0, {%1, %2};" : "=l"(r) : "f"(lo), "f"(hi));
    return r;
}
__device__ __forceinline__ void upk(u64 v, float& lo, float& hi) {
    asm("mov.b64 {%0, %1}, %2;" : "=f"(lo), "=f"(hi) : "l"(v));
}
// Packed dual-FMA on the Blackwell f32x2 pipe (2x FFMA rate)
__device__ __forceinline__ void fma2(u64& d, u64 a, u64 b) {
    asm("fma.rn.f32x2 %0, %1, %2, %0;" : "+l"(d) : "l"(a), "l"(b));
}
__device__ __forceinline__ void cp16(uint32_t dst, const float* src) {
    asm volatile("cp.async.cg.shared.global [%0], [%1], 16;" :: "r"(dst), "l"(src) : "memory");
}
__device__ __forceinline__ void cpcommit() {
    asm volatile("cp.async.commit_group;" ::: "memory");
}
__device__ __forceinline__ void cpwait0() {
    asm volatile("cp.async.wait_group 0;" ::: "memory");
}

// ---------------- kernel 1: transpose features [b][cin][h][w] -> [cin][h][w][b] ----
__global__ void __launch_bounds__(256)
xpose_kernel(const float* __restrict__ features)
{
    __shared__ float t[32][33];
    const int cin = blockIdx.x >> 6;
    const int hh  = blockIdx.x & 63;
    const int ww0 = blockIdx.y << 5;
    const int tx = threadIdx.x & 31;
    const int ty = threadIdx.x >> 5;   // 0..7

    #pragma unroll
    for (int i = 0; i < 4; i++) {
        int b = ty + 8 * i;
        t[b][tx] = features[((b * CIN + cin) * HH + hh) * WW + ww0 + tx];
    }
    __syncthreads();
    #pragma unroll
    for (int i = 0; i < 4; i++) {
        int wwi = ty + 8 * i;
        g_xposed[((cin * HH + hh) * WW + ww0 + wwi) * BATCH + tx] = t[tx][wwi];
    }
}

// ---------------- kernel 2: locally-connected GEMM, 2 w-locations per CTA -----------
__global__ void __launch_bounds__(BLOCK, 4)
lc2d_kernel(const float* __restrict__ weights,
            const float* __restrict__ bias,
            float* __restrict__ out)
{
    extern __shared__ float smem[];
    // x_s[slot][loc][kk][batch]   (32 floats per row, 128B, LDS.128 conflict-free)
    float* x_s = smem;
    // w_t[buf][loc][kk][col^swz]  (k-major, XOR swizzle for conflict-free STS)
    float* w_s = smem + XS_FLOATS;

    const int tid = threadIdx.x;
    const int h   = blockIdx.y;
    const int w0  = blockIdx.x * 2;         // this CTA: locations (h, w0) and (h, w0+1)

    // compute mapping: loc = tid>>6; within loc: bg = batches bg*4.., cq = couts cq*8..
    const int loc = tid >> 6;
    const int t   = tid & 63;
    const int bg  = t & 7;
    const int cq  = t >> 3;                 // 0..7

    // w-loader mapping: per loc 64 threads, 8 float4 each (rows c = cb + 8u)
    const int qq = t & 7;                   // 16B k-segment
    const int cb = t >> 3;                  // 0..7

    const float* wloc  = weights + (size_t)(h * WOUT + w0 + loc) * (COUT * KTOT);
    const float* fbase = g_xposed + (size_t)(h * WW + w0) * BATCH;

    float4 rel[8];   // w register relay (one chunk ahead of smem)

    auto ldg_w = [&](int ch) {
        const float* src = wloc + ch * KCHUNK + qq * 4;
        #pragma unroll
        for (int u = 0; u < 8; u++)
            rel[u] = *(const float4*)(src + (size_t)(cb + 8 * u) * KTOT);
    };
    // k-major store with swizzle col = c ^ ((kk>>2)<<2): STS conflict-free (verified)
    auto sts_w = [&](int buf) {
        float* base = w_s + (buf * 2 + loc) * (KCHUNK * WT);
        #pragma unroll
        for (int u = 0; u < 8; u++) {
            const int c = cb + 8 * u;
            const float* v = &rel[u].x;
            #pragma unroll
            for (int e = 0; e < 4; e++) {
                const int kk = qq * 4 + e;
                base[kk * WT + (c ^ ((kk >> 2) << 2))] = v[e];
            }
        }
    };
    // x gather: 4 coalesced 16B cp.async per thread (both locations)
    auto issue_x = [&](int ch, int slot) {
        #pragma unroll
        for (int s = 0; s < 4; s++) {
            const int idx = tid + s * BLOCK;        // 0..511
            const int l   = idx >> 8;
            const int rem = idx & 255;
            const int k   = rem >> 3;
            const int seg = rem & 7;
            const int r   = ch * KCHUNK + k;
            const int cin = r / 9;
            const int f   = r - cin * 9;
            const int ii  = f / 3;
            const int jj  = f - ii * 3;
            const float* src = fbase + ((size_t)cin * (HH * WW)
                             + ii * WW + l + jj) * BATCH + seg * 4;
            uint32_t dst = (uint32_t)__cvta_generic_to_shared(
                x_s + ((slot * 2 + l) * KCHUNK + k) * BATCH + seg * 4);
            cp16(dst, src);
        }
        cpcommit();
    };

    // ---- prologue ----
    ldg_w(0);
    issue_x(0, 0);
    sts_w(0);
    ldg_w(1);

    u64 acc[4][4];   // [batch b][cout-pair j]
    #pragma unroll
    for (int p = 0; p < 4; p++)
        #pragma unroll
        for (int j = 0; j < 4; j++) acc[p][j] = 0ULL;

    #pragma unroll 1
    for (int ch = 0; ch < NCHUNK; ch++) {
        cpwait0();            // x(ch) landed (issued last iter / prologue)
        __syncthreads();      // publish x(ch), w(ch); old slot/buf now free

        if (ch + 1 < NCHUNK) {
            sts_w((ch + 1) & 1);               // consume rel = w(ch+1)
            if (ch + 2 < NCHUNK) ldg_w(ch + 2);
            issue_x(ch + 1, (ch + 1) & 1);     // overlaps with compute below
        }

        const float* xb = x_s + ((ch & 1) * 2 + loc) * (KCHUNK * BATCH) + bg * 4;
        const float* wb = w_s + ((ch & 1) * 2 + loc) * (KCHUNK * WT);

        #pragma unroll
        for (int kk = 0; kk < KCHUNK; kk++) {
            const int swz = (kk >> 2) << 2;
            // 4 batches: one LDS.128 (8 distinct 16B addrs, 1 wf)
            ulonglong2 xv = *(const ulonglong2*)(xb + kk * BATCH);
            float x0, x1, x2, x3;
            upk(xv.x, x0, x1);
            upk(xv.y, x2, x3);
            u64 xd0 = pk(x0, x0), xd1 = pk(x1, x1);
            u64 xd2 = pk(x2, x2), xd3 = pk(x3, x3);
            // 8 couts as 4 packed pairs: two LDS.128 (4 distinct addrs each, 1 wf)
            ulonglong2 wa = *(const ulonglong2*)(wb + kk * WT + ((cq * 8    ) ^ swz));
            ulonglong2 wd = *(const ulonglong2*)(wb + kk * WT + ((cq * 8 + 4) ^ swz));

            fma2(acc[0][0], xd0, wa.x); fma2(acc[1][0], xd1, wa.x);
            fma2(acc[2][0], xd2, wa.x); fma2(acc[3][0], xd3, wa.x);
            fma2(acc[0][1], xd0, wa.y); fma2(acc[1][1], xd1, wa.y);
            fma2(acc[2][1], xd2, wa.y); fma2(acc[3][1], xd3, wa.y);
            fma2(acc[0][2], xd0, wd.x); fma2(acc[1][2], xd1, wd.x);
            fma2(acc[2][2], xd2, wd.x); fma2(acc[3][2], xd3, wd.x);
            fma2(acc[0][3], xd0, wd.y); fma2(acc[1][3], xd1, wd.y);
            fma2(acc[2][3], xd2, wd.y); fma2(acc[3][3], xd3, wd.y);
        }
    }

    // ---- epilogue: unpack (cout pairs), add bias, scattered STG.32 ----
    const int wabs = w0 + loc;
    const float* bl = bias + (h * WOUT + wabs) * COUT + cq * 8;

    #pragma unroll
    for (int p = 0; p < 4; p++) {
        const int b = bg * 4 + p;
        #pragma unroll
        for (int j = 0; j < 4; j++) {
            const int c = cq * 8 + 2 * j;
            float lo, hi;
            upk(acc[p][j], lo, hi);
            out[((b * COUT + c    ) * HOUT + h) * WOUT + wabs] = lo + bl[2 * j];
            out[((b * COUT + c + 1) * HOUT + h) * WOUT + wabs] = hi + bl[2 * j + 1];
        }
    }
}

extern "C" void kernel_launch(void* const* d_in, const int* in_sizes, int n_in,
                              void* d_out, int out_size)
{
    const float* features = nullptr;
    const float* weights  = nullptr;
    const float* bias     = nullptr;
    for (int i = 0; i < n_in; i++) {
        if      (in_sizes[i] == BATCH * CIN * HH * WW)        features = (const float*)d_in[i];
        else if (in_sizes[i] == HOUT * WOUT * COUT * CIN * 9) weights  = (const float*)d_in[i];
        else if (in_sizes[i] == HOUT * WOUT * COUT)           bias     = (const float*)d_in[i];
    }
    float* out = (float*)d_out;

    cudaFuncSetAttribute(lc2d_kernel,
                         cudaFuncAttributeMaxDynamicSharedMemorySize, SMEM_BYTES);

    // 1) transpose features -> [cin][h][w][batch]
    xpose_kernel<<<dim3(CIN * HH, WW / 32), 256>>>(features);
    // 2) main locally-connected GEMM (2 w-locations per CTA)
    lc2d_kernel<<<dim3(WOUT / 2, HOUT), BLOCK, SMEM_BYTES>>>(weights, bias, out);
}